// round 14
// baseline (speedup 1.0000x reference)
#include <cuda_runtime.h>
#include <cuda_bf16.h>
#include <cstdint>

// Problem constants (fixed-shape problem)
#define B_  4
#define S_  2048
#define D_  1024
#define H_  16
#define DH_ 64
#define M_  (B_ * S_)   // 8192
#define MD_ (M_ * D_)   // 8388608
#define DD_ (D_ * D_)   // 1048576

// ---------------------------------------------------------------------------
// Scratch (device globals: allocation-free, graph-capturable)
// ---------------------------------------------------------------------------
__device__ __nv_bfloat16 g_inh[3 * MD_];  // split inputs (q,k,v) hi
__device__ __nv_bfloat16 g_inl[3 * MD_];  // lo
__device__ __nv_bfloat16 g_wh [4 * DD_];  // split weights (Wq,Wk,Wv,Wo) hi
__device__ __nv_bfloat16 g_wl [4 * DD_];
__device__ __nv_bfloat16 g_ph [3 * MD_];  // projected Q,K,V hi, [B,H,S,Dh]
__device__ __nv_bfloat16 g_pl [3 * MD_];
__device__ __nv_bfloat16 g_oh [MD_];      // attention output hi, [B,S,D]
__device__ __nv_bfloat16 g_ol [MD_];

// ---------------------------------------------------------------------------
// Helpers
// ---------------------------------------------------------------------------
__device__ __forceinline__ uint32_t smem_u32(const void* p) {
    return (uint32_t)__cvta_generic_to_shared(p);
}
__device__ __forceinline__ void ldsm_x4(uint32_t& r0, uint32_t& r1,
                                        uint32_t& r2, uint32_t& r3, uint32_t a) {
    asm volatile("ldmatrix.sync.aligned.m8n8.x4.shared.b16 {%0,%1,%2,%3}, [%4];"
                 : "=r"(r0), "=r"(r1), "=r"(r2), "=r"(r3) : "r"(a));
}
__device__ __forceinline__ void ldsm_x4t(uint32_t& r0, uint32_t& r1,
                                         uint32_t& r2, uint32_t& r3, uint32_t a) {
    asm volatile("ldmatrix.sync.aligned.m8n8.x4.trans.shared.b16 {%0,%1,%2,%3}, [%4];"
                 : "=r"(r0), "=r"(r1), "=r"(r2), "=r"(r3) : "r"(a));
}
__device__ __forceinline__ void mma_bf16(float* d, const uint32_t* a, const uint32_t* b) {
    asm volatile(
        "mma.sync.aligned.m16n8k16.row.col.f32.bf16.bf16.f32 "
        "{%0,%1,%2,%3}, {%4,%5,%6,%7}, {%8,%9}, {%0,%1,%2,%3};"
        : "+f"(d[0]), "+f"(d[1]), "+f"(d[2]), "+f"(d[3])
        : "r"(a[0]), "r"(a[1]), "r"(a[2]), "r"(a[3]), "r"(b[0]), "r"(b[1]));
}
// Split two fp32 into packed bf16 hi-pair and lo-pair (x in low half).
__device__ __forceinline__ void split2(float x, float y, uint32_t& hi, uint32_t& lo) {
    __nv_bfloat16 xh = __float2bfloat16(x);
    __nv_bfloat16 yh = __float2bfloat16(y);
    __nv_bfloat16 xl = __float2bfloat16(x - __bfloat162float(xh));
    __nv_bfloat16 yl = __float2bfloat16(y - __bfloat162float(yh));
    __nv_bfloat162 h2 = __halves2bfloat162(xh, yh);
    __nv_bfloat162 l2 = __halves2bfloat162(xl, yl);
    hi = *(uint32_t*)&h2;
    lo = *(uint32_t*)&l2;
}
__device__ __forceinline__ float sigm(float x) {
    return __fdividef(1.0f, 1.0f + __expf(-x * 0.125f));
}

// ---------------------------------------------------------------------------
// One-time fp32 -> bf16 hi/lo split (grid-stride, float4 granularity)
// ---------------------------------------------------------------------------
__global__ void split_kernel(const float* __restrict__ src,
                             __nv_bfloat16* __restrict__ hi,
                             __nv_bfloat16* __restrict__ lo, int n)
{
    for (int i = (blockIdx.x * blockDim.x + threadIdx.x) * 4; i < n;
         i += gridDim.x * blockDim.x * 4) {
        const float4 v = *(const float4*)(src + i);
        uint32_t h0, l0, h1, l1;
        split2(v.x, v.y, h0, l0);
        split2(v.z, v.w, h1, l1);
        *(uint2*)(hi + i) = make_uint2(h0, h1);
        *(uint2*)(lo + i) = make_uint2(l0, l1);
    }
}

// ---------------------------------------------------------------------------
// GEMM core (NT): C[M,N] = A[M,K] * W[N,K]^T + bias[N], bf16x3, pre-split in.
// M=8192, N=K=1024. CTA 128x128, BK=32, 256 threads (8 warps 2x4).
// MODE 0: C fp32 row-major. MODE 1: C split bf16 hi/lo, scatter [B,H,S,Dh].
// ---------------------------------------------------------------------------
#define AST 40   // smem K-stride (32 + 8 pad) bf16

template <int MODE>
__device__ __forceinline__ void gemm_core(
    const __nv_bfloat16* __restrict__ Ahg, const __nv_bfloat16* __restrict__ Alg,
    const __nv_bfloat16* __restrict__ Whg, const __nv_bfloat16* __restrict__ Wlg,
    const float* __restrict__ bias,
    float* __restrict__ Cf,
    __nv_bfloat16* __restrict__ Ch, __nv_bfloat16* __restrict__ Cl)
{
    __shared__ __align__(16) __nv_bfloat16 sAh[128 * AST];
    __shared__ __align__(16) __nv_bfloat16 sAl[128 * AST];
    __shared__ __align__(16) __nv_bfloat16 sWh[128 * AST];
    __shared__ __align__(16) __nv_bfloat16 sWl[128 * AST];

    const int tid  = threadIdx.x;
    const int lane = tid & 31;
    const int wid  = tid >> 5;
    const int wm   = (wid >> 2) * 64;
    const int wn   = (wid & 3) * 32;
    const int bm   = blockIdx.y * 128;
    const int bn   = blockIdx.x * 128;

    // staging map: per array, 2 uint4 (16B = 8 bf16) per thread per chunk
    int rrow[2], rq[2];
#pragma unroll
    for (int i = 0; i < 2; i++) {
        const int idx = tid + i * 256;
        rrow[i] = idx >> 2;
        rq[i]   = (idx & 3) * 8;
    }

    uint4 pah[2], pal[2], pwh[2], pwl[2];
#pragma unroll
    for (int i = 0; i < 2; i++) {
        pah[i] = *(const uint4*)(Ahg + (size_t)(bm + rrow[i]) * D_ + rq[i]);
        pal[i] = *(const uint4*)(Alg + (size_t)(bm + rrow[i]) * D_ + rq[i]);
        pwh[i] = *(const uint4*)(Whg + (size_t)(bn + rrow[i]) * D_ + rq[i]);
        pwl[i] = *(const uint4*)(Wlg + (size_t)(bn + rrow[i]) * D_ + rq[i]);
    }

    float acc[4][4][4];
#pragma unroll
    for (int mt = 0; mt < 4; mt++)
#pragma unroll
        for (int nt = 0; nt < 4; nt++)
#pragma unroll
            for (int r = 0; r < 4; r++) acc[mt][nt][r] = 0.0f;

    const int a_r = lane & 15;
    const int a_k = (lane >> 4) * 8;
    const int b_r = (lane & 7) + ((lane >> 4) & 1) * 8;
    const int b_k = ((lane >> 3) & 1) * 8;

    for (int k0 = 0; k0 < D_; k0 += 32) {
#pragma unroll
        for (int i = 0; i < 2; i++) {
            const int off = rrow[i] * AST + rq[i];
            *(uint4*)&sAh[off] = pah[i];
            *(uint4*)&sAl[off] = pal[i];
            *(uint4*)&sWh[off] = pwh[i];
            *(uint4*)&sWl[off] = pwl[i];
        }
        __syncthreads();

        if (k0 + 32 < D_) {
#pragma unroll
            for (int i = 0; i < 2; i++) {
                pah[i] = *(const uint4*)(Ahg + (size_t)(bm + rrow[i]) * D_ + k0 + 32 + rq[i]);
                pal[i] = *(const uint4*)(Alg + (size_t)(bm + rrow[i]) * D_ + k0 + 32 + rq[i]);
                pwh[i] = *(const uint4*)(Whg + (size_t)(bn + rrow[i]) * D_ + k0 + 32 + rq[i]);
                pwl[i] = *(const uint4*)(Wlg + (size_t)(bn + rrow[i]) * D_ + k0 + 32 + rq[i]);
            }
        }

#pragma unroll
        for (int ks = 0; ks < 2; ks++) {
            uint32_t Ah[4][4], Al[4][4], Bh[4][2], Bl[4][2];
#pragma unroll
            for (int mt = 0; mt < 4; mt++) {
                const int eo = (wm + mt * 16 + a_r) * AST + ks * 16 + a_k;
                ldsm_x4(Ah[mt][0], Ah[mt][1], Ah[mt][2], Ah[mt][3], smem_u32(&sAh[eo]));
                ldsm_x4(Al[mt][0], Al[mt][1], Al[mt][2], Al[mt][3], smem_u32(&sAl[eo]));
            }
#pragma unroll
            for (int p = 0; p < 2; p++) {
                const int eo = (wn + p * 16 + b_r) * AST + ks * 16 + b_k;
                ldsm_x4(Bh[2 * p][0], Bh[2 * p][1], Bh[2 * p + 1][0], Bh[2 * p + 1][1],
                        smem_u32(&sWh[eo]));
                ldsm_x4(Bl[2 * p][0], Bl[2 * p][1], Bl[2 * p + 1][0], Bl[2 * p + 1][1],
                        smem_u32(&sWl[eo]));
            }
#pragma unroll
            for (int mt = 0; mt < 4; mt++)
#pragma unroll
                for (int nt = 0; nt < 4; nt++) {
                    mma_bf16(acc[mt][nt], Ah[mt], Bh[nt]);
                    mma_bf16(acc[mt][nt], Ah[mt], Bl[nt]);
                    mma_bf16(acc[mt][nt], Al[mt], Bh[nt]);
                }
        }
        __syncthreads();
    }

    // epilogue
#pragma unroll
    for (int mt = 0; mt < 4; mt++) {
        const int r0 = bm + wm + mt * 16 + (lane >> 2);
#pragma unroll
        for (int nt = 0; nt < 4; nt++) {
            const int c0 = bn + wn + nt * 8 + (lane & 3) * 2;
            const float bz0 = bias[c0], bz1 = bias[c0 + 1];
#pragma unroll
            for (int half = 0; half < 2; half++) {
                const int row = r0 + half * 8;
                const float v0 = acc[mt][nt][2 * half]     + bz0;
                const float v1 = acc[mt][nt][2 * half + 1] + bz1;
                if (MODE == 0) {
                    *(float2*)&Cf[(size_t)row * D_ + c0] = make_float2(v0, v1);
                } else {
                    const int bb = row >> 11;
                    const int ss = row & (S_ - 1);
                    const int h  = c0 >> 6;
                    const int dh = c0 & (DH_ - 1);
                    const size_t o = (((size_t)(bb * H_ + h)) * S_ + ss) * DH_ + dh;
                    uint32_t hi, lo;
                    split2(v0, v1, hi, lo);
                    *(uint32_t*)&Ch[o] = hi;
                    *(uint32_t*)&Cl[o] = lo;
                }
            }
        }
    }
}

struct ProjArgs {
    const __nv_bfloat16 *Ah[3], *Al[3], *Wh[3], *Wl[3];
    const float* bias[3];
    __nv_bfloat16 *Ch[3], *Cl[3];
};

__global__ __launch_bounds__(256) void gemm_proj(ProjArgs pa)
{
    const int z = blockIdx.z;
    gemm_core<1>(pa.Ah[z], pa.Al[z], pa.Wh[z], pa.Wl[z], pa.bias[z],
                 nullptr, pa.Ch[z], pa.Cl[z]);
}

__global__ __launch_bounds__(256) void gemm_out(
    const __nv_bfloat16* __restrict__ Ah, const __nv_bfloat16* __restrict__ Al,
    const __nv_bfloat16* __restrict__ Wh, const __nv_bfloat16* __restrict__ Wl,
    const float* __restrict__ bias, float* __restrict__ C)
{
    gemm_core<0>(Ah, Al, Wh, Wl, bias, C, nullptr, nullptr);
}

// ---------------------------------------------------------------------------
// Sigmoid attention, FA2-style: per (b,h): O = sigmoid(QK^T/8) V
// Each warp owns 16 q-rows x full 128-kv tile; P (= sigmoid(S)) stays in
// registers: the m16n8 accumulator fragment pair re-packs directly into the
// m16k16 A-operand fragment (hi/lo bf16 split in regs). No P smem, 2 barriers
// per kv tile. smem = 6 x [128][72] bf16 = 110,592 B dynamic.
// ---------------------------------------------------------------------------
#define QST 72
#define ATT_SMEM (6 * 128 * QST * 2)

__global__ __launch_bounds__(256) void attn_fa(
    const __nv_bfloat16* __restrict__ Qh_g, const __nv_bfloat16* __restrict__ Ql_g,
    const __nv_bfloat16* __restrict__ Kh_g, const __nv_bfloat16* __restrict__ Kl_g,
    const __nv_bfloat16* __restrict__ Vh_g, const __nv_bfloat16* __restrict__ Vl_g,
    __nv_bfloat16* __restrict__ Oh_g, __nv_bfloat16* __restrict__ Ol_g)
{
    extern __shared__ __nv_bfloat16 sm[];
    __nv_bfloat16* Qh = sm;
    __nv_bfloat16* Ql = Qh + 128 * QST;
    __nv_bfloat16* Kh = Ql + 128 * QST;
    __nv_bfloat16* Kl = Kh + 128 * QST;
    __nv_bfloat16* Vh = Kl + 128 * QST;
    __nv_bfloat16* Vl = Vh + 128 * QST;

    const int tid  = threadIdx.x;
    const int lane = tid & 31;
    const int wid  = tid >> 5;
    const int r0   = wid * 16;           // warp's q-row block
    const int bh   = blockIdx.y;
    const int q0   = blockIdx.x * 128;

    const size_t base = (size_t)bh * S_ * DH_;
    const __nv_bfloat16* Qph = Qh_g + base;
    const __nv_bfloat16* Qpl = Ql_g + base;
    const __nv_bfloat16* Kph = Kh_g + base;
    const __nv_bfloat16* Kpl = Kl_g + base;
    const __nv_bfloat16* Vph = Vh_g + base;
    const __nv_bfloat16* Vpl = Vl_g + base;

    // staging map: per array, 4 uint4 per thread (128x64 bf16 tile)
    int srow[4], sq[4];
#pragma unroll
    for (int i = 0; i < 4; i++) {
        const int idx = tid + i * 256;
        srow[i] = idx >> 3;
        sq[i]   = (idx & 7) * 8;
    }

    // load Q hi/lo once
#pragma unroll
    for (int i = 0; i < 4; i++) {
        const size_t go = (size_t)(q0 + srow[i]) * DH_ + sq[i];
        const int    so = srow[i] * QST + sq[i];
        *(uint4*)&Qh[so] = *(const uint4*)(Qph + go);
        *(uint4*)&Ql[so] = *(const uint4*)(Qpl + go);
    }

    // ldmatrix lane offsets
    const int a_r = lane & 15;
    const int a_k = (lane >> 4) * 8;
    const int b_r = (lane & 7) + ((lane >> 4) & 1) * 8;
    const int b_k = ((lane >> 3) & 1) * 8;
    const int v_kv = lane & 15;
    const int v_dh = ((lane >> 4) & 1) * 8;

    float oacc[8][4];
#pragma unroll
    for (int t = 0; t < 8; t++)
#pragma unroll
        for (int r = 0; r < 4; r++) oacc[t][r] = 0.0f;

    for (int j0 = 0; j0 < S_; j0 += 128) {
        __syncthreads();   // prior tile's K/V reads complete
#pragma unroll
        for (int i = 0; i < 4; i++) {
            const size_t go = (size_t)(j0 + srow[i]) * DH_ + sq[i];
            const int    so = srow[i] * QST + sq[i];
            *(uint4*)&Kh[so] = *(const uint4*)(Kph + go);
            *(uint4*)&Kl[so] = *(const uint4*)(Kpl + go);
            *(uint4*)&Vh[so] = *(const uint4*)(Vph + go);
            *(uint4*)&Vl[so] = *(const uint4*)(Vpl + go);
        }
        __syncthreads();

        // ---- Stage 1: S rows r0..r0+15 x 128 kv ----
        float sacc[16][4];
#pragma unroll
        for (int t = 0; t < 16; t++)
#pragma unroll
            for (int r = 0; r < 4; r++) sacc[t][r] = 0.0f;

#pragma unroll
        for (int ks = 0; ks < 4; ks++) {
            uint32_t Afh[4], Afl[4];
            {
                const int eo = (r0 + a_r) * QST + ks * 16 + a_k;
                ldsm_x4(Afh[0], Afh[1], Afh[2], Afh[3], smem_u32(&Qh[eo]));
                ldsm_x4(Afl[0], Afl[1], Afl[2], Afl[3], smem_u32(&Ql[eo]));
            }
#pragma unroll
            for (int p = 0; p < 8; p++) {
                uint32_t Bh0[2], Bh1[2], Bl0[2], Bl1[2];
                const int eo = (p * 16 + b_r) * QST + ks * 16 + b_k;
                ldsm_x4(Bh0[0], Bh0[1], Bh1[0], Bh1[1], smem_u32(&Kh[eo]));
                ldsm_x4(Bl0[0], Bl0[1], Bl1[0], Bl1[1], smem_u32(&Kl[eo]));
                mma_bf16(sacc[2 * p],     Afh, Bh0);
                mma_bf16(sacc[2 * p],     Afh, Bl0);
                mma_bf16(sacc[2 * p],     Afl, Bh0);
                mma_bf16(sacc[2 * p + 1], Afh, Bh1);
                mma_bf16(sacc[2 * p + 1], Afh, Bl1);
                mma_bf16(sacc[2 * p + 1], Afl, Bh1);
            }
        }

        // sigmoid + repack accumulator fragments as A-operand fragments (hi/lo)
        uint32_t Pfh[8][4], Pfl[8][4];
#pragma unroll
        for (int kt = 0; kt < 8; kt++) {
            const int t0 = 2 * kt, t1 = 2 * kt + 1;
            const float p00 = sigm(sacc[t0][0]), p01 = sigm(sacc[t0][1]);
            const float p02 = sigm(sacc[t0][2]), p03 = sigm(sacc[t0][3]);
            const float p10 = sigm(sacc[t1][0]), p11 = sigm(sacc[t1][1]);
            const float p12 = sigm(sacc[t1][2]), p13 = sigm(sacc[t1][3]);
            split2(p00, p01, Pfh[kt][0], Pfl[kt][0]);
            split2(p02, p03, Pfh[kt][1], Pfl[kt][1]);
            split2(p10, p11, Pfh[kt][2], Pfl[kt][2]);
            split2(p12, p13, Pfh[kt][3], Pfl[kt][3]);
        }

        // ---- Stage 2: O += P V ----
#pragma unroll
        for (int kt = 0; kt < 8; kt++) {
#pragma unroll
            for (int nn = 0; nn < 4; nn++) {
                uint32_t Bh0[2], Bh1[2], Bl0[2], Bl1[2];
                const int eo = (kt * 16 + v_kv) * QST + nn * 16 + v_dh;
                ldsm_x4t(Bh0[0], Bh0[1], Bh1[0], Bh1[1], smem_u32(&Vh[eo]));
                ldsm_x4t(Bl0[0], Bl0[1], Bl1[0], Bl1[1], smem_u32(&Vl[eo]));
                mma_bf16(oacc[2 * nn],     Pfh[kt], Bh0);
                mma_bf16(oacc[2 * nn],     Pfh[kt], Bl0);
                mma_bf16(oacc[2 * nn],     Pfl[kt], Bh0);
                mma_bf16(oacc[2 * nn + 1], Pfh[kt], Bh1);
                mma_bf16(oacc[2 * nn + 1], Pfh[kt], Bl1);
                mma_bf16(oacc[2 * nn + 1], Pfl[kt], Bh1);
            }
        }
    }

    // epilogue: split O -> hi/lo bf16, concat layout [B,S,D]
    const int bb = bh >> 4;
    const int h  = bh & (H_ - 1);
    const int g  = lane >> 2;
    const int c2 = (lane & 3) * 2;
#pragma unroll
    for (int t = 0; t < 8; t++) {
        const int dh = 8 * t + c2;
#pragma unroll
        for (int half = 0; half < 2; half++) {
            const int srw = q0 + r0 + g + half * 8;
            const size_t o = ((size_t)bb * S_ + srw) * D_ + h * DH_ + dh;
            uint32_t hi, lo;
            split2(oacc[t][2 * half], oacc[t][2 * half + 1], hi, lo);
            *(uint32_t*)&Oh_g[o] = hi;
            *(uint32_t*)&Ol_g[o] = lo;
        }
    }
}

// ---------------------------------------------------------------------------
// Launcher
// ---------------------------------------------------------------------------
extern "C" void kernel_launch(void* const* d_in, const int* in_sizes, int n_in,
                              void* d_out, int out_size)
{
    const float* q  = (const float*)d_in[0];
    const float* k  = (const float*)d_in[1];
    const float* v  = (const float*)d_in[2];
    const float* Wq = (const float*)d_in[3];
    const float* bq = (const float*)d_in[4];
    const float* Wk = (const float*)d_in[5];
    const float* bk = (const float*)d_in[6];
    const float* Wv = (const float*)d_in[7];
    const float* bv = (const float*)d_in[8];
    const float* Wo = (const float*)d_in[9];
    const float* bo = (const float*)d_in[10];
    float* out = (float*)d_out;

    __nv_bfloat16 *inh, *inl, *wh, *wl, *ph, *pl, *oh, *ol;
    cudaGetSymbolAddress((void**)&inh, g_inh);
    cudaGetSymbolAddress((void**)&inl, g_inl);
    cudaGetSymbolAddress((void**)&wh,  g_wh);
    cudaGetSymbolAddress((void**)&wl,  g_wl);
    cudaGetSymbolAddress((void**)&ph,  g_ph);
    cudaGetSymbolAddress((void**)&pl,  g_pl);
    cudaGetSymbolAddress((void**)&oh,  g_oh);
    cudaGetSymbolAddress((void**)&ol,  g_ol);

    // one-time splits
    split_kernel<<<2048, 256>>>(q,  inh + 0 * MD_, inl + 0 * MD_, MD_);
    split_kernel<<<2048, 256>>>(k,  inh + 1 * MD_, inl + 1 * MD_, MD_);
    split_kernel<<<2048, 256>>>(v,  inh + 2 * MD_, inl + 2 * MD_, MD_);
    split_kernel<<<512, 256>>>(Wq, wh + 0 * DD_, wl + 0 * DD_, DD_);
    split_kernel<<<512, 256>>>(Wk, wh + 1 * DD_, wl + 1 * DD_, DD_);
    split_kernel<<<512, 256>>>(Wv, wh + 2 * DD_, wl + 2 * DD_, DD_);
    split_kernel<<<512, 256>>>(Wo, wh + 3 * DD_, wl + 3 * DD_, DD_);

    // fused Q/K/V projections (grid.z = 3)
    ProjArgs pa;
    const float* biases[3] = {bq, bk, bv};
    for (int z = 0; z < 3; z++) {
        pa.Ah[z] = inh + (size_t)z * MD_;
        pa.Al[z] = inl + (size_t)z * MD_;
        pa.Wh[z] = wh + (size_t)z * DD_;
        pa.Wl[z] = wl + (size_t)z * DD_;
        pa.bias[z] = biases[z];
        pa.Ch[z] = ph + (size_t)z * MD_;
        pa.Cl[z] = pl + (size_t)z * MD_;
    }
    gemm_proj<<<dim3(D_ / 128, M_ / 128, 3), 256>>>(pa);

    // attention
    cudaFuncSetAttribute(attn_fa, cudaFuncAttributeMaxDynamicSharedMemorySize, ATT_SMEM);
    attn_fa<<<dim3(S_ / 128, B_ * H_), 256, ATT_SMEM>>>(
        ph + 0 * MD_, pl + 0 * MD_,
        ph + 1 * MD_, pl + 1 * MD_,
        ph + 2 * MD_, pl + 2 * MD_,
        oh, ol);

    // output projection
    gemm_out<<<dim3(D_ / 128, M_ / 128), 256>>>(oh, ol, wh + 3 * DD_, wl + 3 * DD_, bo, out);
}

// round 15
// speedup vs baseline: 1.0520x; 1.0520x over previous
#include <cuda_runtime.h>
#include <cuda_bf16.h>
#include <cstdint>

// Problem constants (fixed-shape problem)
#define B_  4
#define S_  2048
#define D_  1024
#define H_  16
#define DH_ 64
#define M_  (B_ * S_)   // 8192
#define MD_ (M_ * D_)   // 8388608
#define DD_ (D_ * D_)   // 1048576

// ---------------------------------------------------------------------------
// Scratch (device globals: allocation-free, graph-capturable)
// ---------------------------------------------------------------------------
__device__ __nv_bfloat16 g_inh[3 * MD_];  // split inputs (q,k,v) hi
__device__ __nv_bfloat16 g_inl[3 * MD_];  // lo
__device__ __nv_bfloat16 g_wh [4 * DD_];  // split weights (Wq,Wk,Wv,Wo) hi
__device__ __nv_bfloat16 g_wl [4 * DD_];
__device__ __nv_bfloat16 g_ph [3 * MD_];  // projected Q,K,V hi, [B,H,S,Dh]
__device__ __nv_bfloat16 g_pl [3 * MD_];
__device__ __nv_bfloat16 g_oh [MD_];      // attention output hi, [B,S,D]
__device__ __nv_bfloat16 g_ol [MD_];

// ---------------------------------------------------------------------------
// Helpers
// ---------------------------------------------------------------------------
__device__ __forceinline__ uint32_t smem_u32(const void* p) {
    return (uint32_t)__cvta_generic_to_shared(p);
}
__device__ __forceinline__ void cp16(void* dst_smem, const void* src) {
    asm volatile("cp.async.cg.shared.global [%0], [%1], 16;"
                 :: "r"(smem_u32(dst_smem)), "l"(src));
}
#define CP_COMMIT() asm volatile("cp.async.commit_group;")
#define CP_WAIT(n)  asm volatile("cp.async.wait_group %0;" :: "n"(n))

__device__ __forceinline__ void ldsm_x4(uint32_t& r0, uint32_t& r1,
                                        uint32_t& r2, uint32_t& r3, uint32_t a) {
    asm volatile("ldmatrix.sync.aligned.m8n8.x4.shared.b16 {%0,%1,%2,%3}, [%4];"
                 : "=r"(r0), "=r"(r1), "=r"(r2), "=r"(r3) : "r"(a));
}
__device__ __forceinline__ void ldsm_x4t(uint32_t& r0, uint32_t& r1,
                                         uint32_t& r2, uint32_t& r3, uint32_t a) {
    asm volatile("ldmatrix.sync.aligned.m8n8.x4.trans.shared.b16 {%0,%1,%2,%3}, [%4];"
                 : "=r"(r0), "=r"(r1), "=r"(r2), "=r"(r3) : "r"(a));
}
__device__ __forceinline__ void mma_bf16(float* d, const uint32_t* a, const uint32_t* b) {
    asm volatile(
        "mma.sync.aligned.m16n8k16.row.col.f32.bf16.bf16.f32 "
        "{%0,%1,%2,%3}, {%4,%5,%6,%7}, {%8,%9}, {%0,%1,%2,%3};"
        : "+f"(d[0]), "+f"(d[1]), "+f"(d[2]), "+f"(d[3])
        : "r"(a[0]), "r"(a[1]), "r"(a[2]), "r"(a[3]), "r"(b[0]), "r"(b[1]));
}
// Split two fp32 into packed bf16 hi-pair and lo-pair (x in low half).
__device__ __forceinline__ void split2(float x, float y, uint32_t& hi, uint32_t& lo) {
    __nv_bfloat16 xh = __float2bfloat16(x);
    __nv_bfloat16 yh = __float2bfloat16(y);
    __nv_bfloat16 xl = __float2bfloat16(x - __bfloat162float(xh));
    __nv_bfloat16 yl = __float2bfloat16(y - __bfloat162float(yh));
    __nv_bfloat162 h2 = __halves2bfloat162(xh, yh);
    __nv_bfloat162 l2 = __halves2bfloat162(xl, yl);
    hi = *(uint32_t*)&h2;
    lo = *(uint32_t*)&l2;
}
__device__ __forceinline__ float sigm(float x) {
    return __fdividef(1.0f, 1.0f + __expf(-x * 0.125f));
}

// ---------------------------------------------------------------------------
// One-time fp32 -> bf16 hi/lo split (grid-stride, float4 granularity)
// ---------------------------------------------------------------------------
__global__ void split_kernel(const float* __restrict__ src,
                             __nv_bfloat16* __restrict__ hi,
                             __nv_bfloat16* __restrict__ lo, int n)
{
    for (int i = (blockIdx.x * blockDim.x + threadIdx.x) * 4; i < n;
         i += gridDim.x * blockDim.x * 4) {
        const float4 v = *(const float4*)(src + i);
        uint32_t h0, l0, h1, l1;
        split2(v.x, v.y, h0, l0);
        split2(v.z, v.w, h1, l1);
        *(uint2*)(hi + i) = make_uint2(h0, h1);
        *(uint2*)(lo + i) = make_uint2(l0, l1);
    }
}

// ---------------------------------------------------------------------------
// GEMM core (NT): C[M,N] = A[M,K] * W[N,K]^T + bias[N], bf16x3, pre-split in.
// CTA 128x128, BK=32, 256 threads (8 warps 2x4). cp.async 2-stage pipeline.
// MODE 0: C fp32 row-major. MODE 1: C split bf16 hi/lo, scatter [B,H,S,Dh].
// Dynamic smem: 2 stages x 4 arrays x 128*AST bf16 = 81,920 B.
// ---------------------------------------------------------------------------
#define AST 40                      // smem K-stride (32 + 8 pad) bf16
#define GARR (128 * AST)            // elems per array per stage
#define GEMM_SMEM (2 * 4 * GARR * 2)

template <int MODE>
__device__ __forceinline__ void gemm_core(
    const __nv_bfloat16* __restrict__ Ahg, const __nv_bfloat16* __restrict__ Alg,
    const __nv_bfloat16* __restrict__ Whg, const __nv_bfloat16* __restrict__ Wlg,
    const float* __restrict__ bias,
    float* __restrict__ Cf,
    __nv_bfloat16* __restrict__ Ch, __nv_bfloat16* __restrict__ Cl)
{
    extern __shared__ __nv_bfloat16 smg[];
    // stage s: [sAh sAl sWh sWl]
    const int tid  = threadIdx.x;
    const int lane = tid & 31;
    const int wid  = tid >> 5;
    const int wm   = (wid >> 2) * 64;
    const int wn   = (wid & 3) * 32;
    const int bm   = blockIdx.y * 128;
    const int bn   = blockIdx.x * 128;

    // staging map: per array, 2 x 16B chunks per thread per k-chunk
    int rrow[2], rq[2];
#pragma unroll
    for (int i = 0; i < 2; i++) {
        const int idx = tid + i * 256;
        rrow[i] = idx >> 2;
        rq[i]   = (idx & 3) * 8;
    }

    auto issue = [&](int k0, int s) {
        __nv_bfloat16* sAh = smg + (size_t)s * 4 * GARR;
        __nv_bfloat16* sAl = sAh + GARR;
        __nv_bfloat16* sWh = sAl + GARR;
        __nv_bfloat16* sWl = sWh + GARR;
#pragma unroll
        for (int i = 0; i < 2; i++) {
            const size_t ga = (size_t)(bm + rrow[i]) * D_ + k0 + rq[i];
            const size_t gw = (size_t)(bn + rrow[i]) * D_ + k0 + rq[i];
            const int    so = rrow[i] * AST + rq[i];
            cp16(sAh + so, Ahg + ga);
            cp16(sAl + so, Alg + ga);
            cp16(sWh + so, Whg + gw);
            cp16(sWl + so, Wlg + gw);
        }
    };

    float acc[4][4][4];
#pragma unroll
    for (int mt = 0; mt < 4; mt++)
#pragma unroll
        for (int nt = 0; nt < 4; nt++)
#pragma unroll
            for (int r = 0; r < 4; r++) acc[mt][nt][r] = 0.0f;

    const int a_r = lane & 15;
    const int a_k = (lane >> 4) * 8;
    const int b_r = (lane & 7) + ((lane >> 4) & 1) * 8;
    const int b_k = ((lane >> 3) & 1) * 8;

    issue(0, 0);
    CP_COMMIT();

    const int NCH = D_ / 32;   // 32 k-chunks
    for (int kt = 0; kt < NCH; kt++) {
        const int cur = kt & 1;
        if (kt + 1 < NCH) {
            issue((kt + 1) * 32, cur ^ 1);
            CP_COMMIT();
            CP_WAIT(1);
        } else {
            CP_WAIT(0);
        }
        __syncthreads();

        const __nv_bfloat16* sAh = smg + (size_t)cur * 4 * GARR;
        const __nv_bfloat16* sAl = sAh + GARR;
        const __nv_bfloat16* sWh = sAl + GARR;
        const __nv_bfloat16* sWl = sWh + GARR;

#pragma unroll
        for (int ks = 0; ks < 2; ks++) {
            uint32_t Ah[4][4], Al[4][4], Bh[4][2], Bl[4][2];
#pragma unroll
            for (int mt = 0; mt < 4; mt++) {
                const int eo = (wm + mt * 16 + a_r) * AST + ks * 16 + a_k;
                ldsm_x4(Ah[mt][0], Ah[mt][1], Ah[mt][2], Ah[mt][3], smem_u32(&sAh[eo]));
                ldsm_x4(Al[mt][0], Al[mt][1], Al[mt][2], Al[mt][3], smem_u32(&sAl[eo]));
            }
#pragma unroll
            for (int p = 0; p < 2; p++) {
                const int eo = (wn + p * 16 + b_r) * AST + ks * 16 + b_k;
                ldsm_x4(Bh[2 * p][0], Bh[2 * p][1], Bh[2 * p + 1][0], Bh[2 * p + 1][1],
                        smem_u32(&sWh[eo]));
                ldsm_x4(Bl[2 * p][0], Bl[2 * p][1], Bl[2 * p + 1][0], Bl[2 * p + 1][1],
                        smem_u32(&sWl[eo]));
            }
#pragma unroll
            for (int mt = 0; mt < 4; mt++)
#pragma unroll
                for (int nt = 0; nt < 4; nt++) {
                    mma_bf16(acc[mt][nt], Ah[mt], Bh[nt]);
                    mma_bf16(acc[mt][nt], Ah[mt], Bl[nt]);
                    mma_bf16(acc[mt][nt], Al[mt], Bh[nt]);
                }
        }
        __syncthreads();
    }

    // epilogue
#pragma unroll
    for (int mt = 0; mt < 4; mt++) {
        const int r0 = bm + wm + mt * 16 + (lane >> 2);
#pragma unroll
        for (int nt = 0; nt < 4; nt++) {
            const int c0 = bn + wn + nt * 8 + (lane & 3) * 2;
            const float bz0 = bias[c0], bz1 = bias[c0 + 1];
#pragma unroll
            for (int half = 0; half < 2; half++) {
                const int row = r0 + half * 8;
                const float v0 = acc[mt][nt][2 * half]     + bz0;
                const float v1 = acc[mt][nt][2 * half + 1] + bz1;
                if (MODE == 0) {
                    *(float2*)&Cf[(size_t)row * D_ + c0] = make_float2(v0, v1);
                } else {
                    const int bb = row >> 11;
                    const int ss = row & (S_ - 1);
                    const int h  = c0 >> 6;
                    const int dh = c0 & (DH_ - 1);
                    const size_t o = (((size_t)(bb * H_ + h)) * S_ + ss) * DH_ + dh;
                    uint32_t hi, lo;
                    split2(v0, v1, hi, lo);
                    *(uint32_t*)&Ch[o] = hi;
                    *(uint32_t*)&Cl[o] = lo;
                }
            }
        }
    }
}

struct ProjArgs {
    const __nv_bfloat16 *Ah[3], *Al[3], *Wh[3], *Wl[3];
    const float* bias[3];
    __nv_bfloat16 *Ch[3], *Cl[3];
};

__global__ __launch_bounds__(256) void gemm_proj(ProjArgs pa)
{
    const int z = blockIdx.z;
    gemm_core<1>(pa.Ah[z], pa.Al[z], pa.Wh[z], pa.Wl[z], pa.bias[z],
                 nullptr, pa.Ch[z], pa.Cl[z]);
}

__global__ __launch_bounds__(256) void gemm_out(
    const __nv_bfloat16* __restrict__ Ah, const __nv_bfloat16* __restrict__ Al,
    const __nv_bfloat16* __restrict__ Wh, const __nv_bfloat16* __restrict__ Wl,
    const float* __restrict__ bias, float* __restrict__ C)
{
    gemm_core<0>(Ah, Al, Wh, Wl, bias, C, nullptr, nullptr);
}

// ---------------------------------------------------------------------------
// Sigmoid attention, FA2-style with cp.async 2-stage K/V pipeline.
// Per (b,h): O = sigmoid(QK^T/8) V. Each warp: 16 q-rows x 128 kv; P stays in
// registers (accumulator fragment == A-operand fragment).
// Dynamic smem: Q hi/lo + 2 stages x (K,V hi/lo) = 10 x 18,432 B = 184,320 B.
// ---------------------------------------------------------------------------
#define QST 72
#define SARR (128 * QST)            // elems per array
#define ATT_SMEM (10 * SARR * 2)

__global__ __launch_bounds__(256) void attn_fa(
    const __nv_bfloat16* __restrict__ Qh_g, const __nv_bfloat16* __restrict__ Ql_g,
    const __nv_bfloat16* __restrict__ Kh_g, const __nv_bfloat16* __restrict__ Kl_g,
    const __nv_bfloat16* __restrict__ Vh_g, const __nv_bfloat16* __restrict__ Vl_g,
    __nv_bfloat16* __restrict__ Oh_g, __nv_bfloat16* __restrict__ Ol_g)
{
    extern __shared__ __nv_bfloat16 sm[];
    __nv_bfloat16* Qh = sm;
    __nv_bfloat16* Ql = Qh + SARR;
    // stage s arrays: Kh,Kl,Vh,Vl at sm + (2 + 4s + {0..3}) * SARR

    const int tid  = threadIdx.x;
    const int lane = tid & 31;
    const int wid  = tid >> 5;
    const int r0   = wid * 16;
    const int bh   = blockIdx.y;
    const int q0   = blockIdx.x * 128;

    const size_t base = (size_t)bh * S_ * DH_;
    const __nv_bfloat16* Qph = Qh_g + base;
    const __nv_bfloat16* Qpl = Ql_g + base;
    const __nv_bfloat16* Kph = Kh_g + base;
    const __nv_bfloat16* Kpl = Kl_g + base;
    const __nv_bfloat16* Vph = Vh_g + base;
    const __nv_bfloat16* Vpl = Vl_g + base;

    // staging map: per array, 4 x 16B per thread (128x64 bf16 tile)
    int srow[4], sq[4];
#pragma unroll
    for (int i = 0; i < 4; i++) {
        const int idx = tid + i * 256;
        srow[i] = idx >> 3;
        sq[i]   = (idx & 7) * 8;
    }

    auto issue_kv = [&](int j0, int s) {
        __nv_bfloat16* Kh = sm + (size_t)(2 + 4 * s) * SARR;
        __nv_bfloat16* Kl = Kh + SARR;
        __nv_bfloat16* Vh = Kl + SARR;
        __nv_bfloat16* Vl = Vh + SARR;
#pragma unroll
        for (int i = 0; i < 4; i++) {
            const size_t go = (size_t)(j0 + srow[i]) * DH_ + sq[i];
            const int    so = srow[i] * QST + sq[i];
            cp16(Kh + so, Kph + go);
            cp16(Kl + so, Kpl + go);
            cp16(Vh + so, Vph + go);
            cp16(Vl + so, Vpl + go);
        }
    };

    // prologue: async Q + tile 0 (one group)
#pragma unroll
    for (int i = 0; i < 4; i++) {
        const size_t go = (size_t)(q0 + srow[i]) * DH_ + sq[i];
        const int    so = srow[i] * QST + sq[i];
        cp16(Qh + so, Qph + go);
        cp16(Ql + so, Qpl + go);
    }
    issue_kv(0, 0);
    CP_COMMIT();

    // ldmatrix lane offsets
    const int a_r = lane & 15;
    const int a_k = (lane >> 4) * 8;
    const int b_r = (lane & 7) + ((lane >> 4) & 1) * 8;
    const int b_k = ((lane >> 3) & 1) * 8;
    const int v_kv = lane & 15;
    const int v_dh = ((lane >> 4) & 1) * 8;

    float oacc[8][4];
#pragma unroll
    for (int t = 0; t < 8; t++)
#pragma unroll
        for (int r = 0; r < 4; r++) oacc[t][r] = 0.0f;

    const int NT = S_ / 128;   // 16 kv tiles
    for (int jt = 0; jt < NT; jt++) {
        const int cur = jt & 1;
        if (jt + 1 < NT) {
            issue_kv((jt + 1) * 128, cur ^ 1);
            CP_COMMIT();
            CP_WAIT(1);
        } else {
            CP_WAIT(0);
        }
        __syncthreads();

        const __nv_bfloat16* Kh = sm + (size_t)(2 + 4 * cur) * SARR;
        const __nv_bfloat16* Kl = Kh + SARR;
        const __nv_bfloat16* Vh = Kl + SARR;
        const __nv_bfloat16* Vl = Vh + SARR;

        // ---- Stage 1: S rows r0..r0+15 x 128 kv ----
        float sacc[16][4];
#pragma unroll
        for (int t = 0; t < 16; t++)
#pragma unroll
            for (int r = 0; r < 4; r++) sacc[t][r] = 0.0f;

#pragma unroll
        for (int ks = 0; ks < 4; ks++) {
            uint32_t Afh[4], Afl[4];
            {
                const int eo = (r0 + a_r) * QST + ks * 16 + a_k;
                ldsm_x4(Afh[0], Afh[1], Afh[2], Afh[3], smem_u32(&Qh[eo]));
                ldsm_x4(Afl[0], Afl[1], Afl[2], Afl[3], smem_u32(&Ql[eo]));
            }
#pragma unroll
            for (int p = 0; p < 8; p++) {
                uint32_t Bh0[2], Bh1[2], Bl0[2], Bl1[2];
                const int eo = (p * 16 + b_r) * QST + ks * 16 + b_k;
                ldsm_x4(Bh0[0], Bh0[1], Bh1[0], Bh1[1], smem_u32(&Kh[eo]));
                ldsm_x4(Bl0[0], Bl0[1], Bl1[0], Bl1[1], smem_u32(&Kl[eo]));
                mma_bf16(sacc[2 * p],     Afh, Bh0);
                mma_bf16(sacc[2 * p],     Afh, Bl0);
                mma_bf16(sacc[2 * p],     Afl, Bh0);
                mma_bf16(sacc[2 * p + 1], Afh, Bh1);
                mma_bf16(sacc[2 * p + 1], Afh, Bl1);
                mma_bf16(sacc[2 * p + 1], Afl, Bh1);
            }
        }

        // sigmoid + repack accumulator fragments as A-operand fragments
        uint32_t Pfh[8][4], Pfl[8][4];
#pragma unroll
        for (int kt = 0; kt < 8; kt++) {
            const int t0 = 2 * kt, t1 = 2 * kt + 1;
            const float p00 = sigm(sacc[t0][0]), p01 = sigm(sacc[t0][1]);
            const float p02 = sigm(sacc[t0][2]), p03 = sigm(sacc[t0][3]);
            const float p10 = sigm(sacc[t1][0]), p11 = sigm(sacc[t1][1]);
            const float p12 = sigm(sacc[t1][2]), p13 = sigm(sacc[t1][3]);
            split2(p00, p01, Pfh[kt][0], Pfl[kt][0]);
            split2(p02, p03, Pfh[kt][1], Pfl[kt][1]);
            split2(p10, p11, Pfh[kt][2], Pfl[kt][2]);
            split2(p12, p13, Pfh[kt][3], Pfl[kt][3]);
        }

        // ---- Stage 2: O += P V ----
#pragma unroll
        for (int kt = 0; kt < 8; kt++) {
#pragma unroll
            for (int nn = 0; nn < 4; nn++) {
                uint32_t Bh0[2], Bh1[2], Bl0[2], Bl1[2];
                const int eo = (kt * 16 + v_kv) * QST + nn * 16 + v_dh;
                ldsm_x4t(Bh0[0], Bh0[1], Bh1[0], Bh1[1], smem_u32(&Vh[eo]));
                ldsm_x4t(Bl0[0], Bl0[1], Bl1[0], Bl1[1], smem_u32(&Vl[eo]));
                mma_bf16(oacc[2 * nn],     Pfh[kt], Bh0);
                mma_bf16(oacc[2 * nn],     Pfh[kt], Bl0);
                mma_bf16(oacc[2 * nn],     Pfl[kt], Bh0);
                mma_bf16(oacc[2 * nn + 1], Pfh[kt], Bh1);
                mma_bf16(oacc[2 * nn + 1], Pfh[kt], Bl1);
                mma_bf16(oacc[2 * nn + 1], Pfl[kt], Bh1);
            }
        }
        __syncthreads();
    }

    // epilogue: split O -> hi/lo bf16, concat layout [B,S,D]
    const int bb = bh >> 4;
    const int h  = bh & (H_ - 1);
    const int g  = lane >> 2;
    const int c2 = (lane & 3) * 2;
#pragma unroll
    for (int t = 0; t < 8; t++) {
        const int dh = 8 * t + c2;
#pragma unroll
        for (int half = 0; half < 2; half++) {
            const int srw = q0 + r0 + g + half * 8;
            const size_t o = ((size_t)bb * S_ + srw) * D_ + h * DH_ + dh;
            uint32_t hi, lo;
            split2(oacc[t][2 * half], oacc[t][2 * half + 1], hi, lo);
            *(uint32_t*)&Oh_g[o] = hi;
            *(uint32_t*)&Ol_g[o] = lo;
        }
    }
}

// ---------------------------------------------------------------------------
// Launcher
// ---------------------------------------------------------------------------
extern "C" void kernel_launch(void* const* d_in, const int* in_sizes, int n_in,
                              void* d_out, int out_size)
{
    const float* q  = (const float*)d_in[0];
    const float* k  = (const float*)d_in[1];
    const float* v  = (const float*)d_in[2];
    const float* Wq = (const float*)d_in[3];
    const float* bq = (const float*)d_in[4];
    const float* Wk = (const float*)d_in[5];
    const float* bk = (const float*)d_in[6];
    const float* Wv = (const float*)d_in[7];
    const float* bv = (const float*)d_in[8];
    const float* Wo = (const float*)d_in[9];
    const float* bo = (const float*)d_in[10];
    float* out = (float*)d_out;

    __nv_bfloat16 *inh, *inl, *wh, *wl, *ph, *pl, *oh, *ol;
    cudaGetSymbolAddress((void**)&inh, g_inh);
    cudaGetSymbolAddress((void**)&inl, g_inl);
    cudaGetSymbolAddress((void**)&wh,  g_wh);
    cudaGetSymbolAddress((void**)&wl,  g_wl);
    cudaGetSymbolAddress((void**)&ph,  g_ph);
    cudaGetSymbolAddress((void**)&pl,  g_pl);
    cudaGetSymbolAddress((void**)&oh,  g_oh);
    cudaGetSymbolAddress((void**)&ol,  g_ol);

    // one-time splits
    split_kernel<<<2048, 256>>>(q,  inh + 0 * MD_, inl + 0 * MD_, MD_);
    split_kernel<<<2048, 256>>>(k,  inh + 1 * MD_, inl + 1 * MD_, MD_);
    split_kernel<<<2048, 256>>>(v,  inh + 2 * MD_, inl + 2 * MD_, MD_);
    split_kernel<<<512, 256>>>(Wq, wh + 0 * DD_, wl + 0 * DD_, DD_);
    split_kernel<<<512, 256>>>(Wk, wh + 1 * DD_, wl + 1 * DD_, DD_);
    split_kernel<<<512, 256>>>(Wv, wh + 2 * DD_, wl + 2 * DD_, DD_);
    split_kernel<<<512, 256>>>(Wo, wh + 3 * DD_, wl + 3 * DD_, DD_);

    // fused Q/K/V projections (grid.z = 3)
    ProjArgs pa;
    const float* biases[3] = {bq, bk, bv};
    for (int z = 0; z < 3; z++) {
        pa.Ah[z] = inh + (size_t)z * MD_;
        pa.Al[z] = inl + (size_t)z * MD_;
        pa.Wh[z] = wh + (size_t)z * DD_;
        pa.Wl[z] = wl + (size_t)z * DD_;
        pa.bias[z] = biases[z];
        pa.Ch[z] = ph + (size_t)z * MD_;
        pa.Cl[z] = pl + (size_t)z * MD_;
    }
    cudaFuncSetAttribute(gemm_proj, cudaFuncAttributeMaxDynamicSharedMemorySize, GEMM_SMEM);
    gemm_proj<<<dim3(D_ / 128, M_ / 128, 3), 256, GEMM_SMEM>>>(pa);

    // attention
    cudaFuncSetAttribute(attn_fa, cudaFuncAttributeMaxDynamicSharedMemorySize, ATT_SMEM);
    attn_fa<<<dim3(S_ / 128, B_ * H_), 256, ATT_SMEM>>>(
        ph + 0 * MD_, pl + 0 * MD_,
        ph + 1 * MD_, pl + 1 * MD_,
        ph + 2 * MD_, pl + 2 * MD_,
        oh, ol);

    // output projection
    cudaFuncSetAttribute(gemm_out, cudaFuncAttributeMaxDynamicSharedMemorySize, GEMM_SMEM);
    gemm_out<<<dim3(D_ / 128, M_ / 128), 256, GEMM_SMEM>>>(
        oh, ol, wh + 3 * DD_, wl + 3 * DD_, bo, out);
}

// round 16
// speedup vs baseline: 1.0781x; 1.0248x over previous
#include <cuda_runtime.h>
#include <cuda_bf16.h>
#include <cstdint>

// Problem constants (fixed-shape problem)
#define B_  4
#define S_  2048
#define D_  1024
#define H_  16
#define DH_ 64
#define M_  (B_ * S_)   // 8192
#define MD_ (M_ * D_)   // 8388608
#define DD_ (D_ * D_)   // 1048576

// ---------------------------------------------------------------------------
// Scratch (device globals: allocation-free, graph-capturable)
// ---------------------------------------------------------------------------
__device__ __nv_bfloat16 g_inh[3 * MD_];  // split inputs (q,k,v) hi
__device__ __nv_bfloat16 g_inl[3 * MD_];  // lo
__device__ __nv_bfloat16 g_wh [4 * DD_];  // split weights (Wq,Wk,Wv,Wo) hi
__device__ __nv_bfloat16 g_wl [4 * DD_];
__device__ __nv_bfloat16 g_ph [3 * MD_];  // projected Q,K,V hi, [B,H,S,Dh]
__device__ __nv_bfloat16 g_pl [3 * MD_];
__device__ __nv_bfloat16 g_oh [MD_];      // attention output hi, [B,S,D]
__device__ __nv_bfloat16 g_ol [MD_];

// ---------------------------------------------------------------------------
// Helpers
// ---------------------------------------------------------------------------
__device__ __forceinline__ uint32_t smem_u32(const void* p) {
    return (uint32_t)__cvta_generic_to_shared(p);
}
__device__ __forceinline__ void cp16(void* dst_smem, const void* src) {
    asm volatile("cp.async.cg.shared.global [%0], [%1], 16;"
                 :: "r"(smem_u32(dst_smem)), "l"(src));
}
#define CP_COMMIT() asm volatile("cp.async.commit_group;")
#define CP_WAIT(n)  asm volatile("cp.async.wait_group %0;" :: "n"(n))

__device__ __forceinline__ void ldsm_x4(uint32_t& r0, uint32_t& r1,
                                        uint32_t& r2, uint32_t& r3, uint32_t a) {
    asm volatile("ldmatrix.sync.aligned.m8n8.x4.shared.b16 {%0,%1,%2,%3}, [%4];"
                 : "=r"(r0), "=r"(r1), "=r"(r2), "=r"(r3) : "r"(a));
}
__device__ __forceinline__ void ldsm_x4t(uint32_t& r0, uint32_t& r1,
                                         uint32_t& r2, uint32_t& r3, uint32_t a) {
    asm volatile("ldmatrix.sync.aligned.m8n8.x4.trans.shared.b16 {%0,%1,%2,%3}, [%4];"
                 : "=r"(r0), "=r"(r1), "=r"(r2), "=r"(r3) : "r"(a));
}
__device__ __forceinline__ void mma_bf16(float* d, const uint32_t* a, const uint32_t* b) {
    asm volatile(
        "mma.sync.aligned.m16n8k16.row.col.f32.bf16.bf16.f32 "
        "{%0,%1,%2,%3}, {%4,%5,%6,%7}, {%8,%9}, {%0,%1,%2,%3};"
        : "+f"(d[0]), "+f"(d[1]), "+f"(d[2]), "+f"(d[3])
        : "r"(a[0]), "r"(a[1]), "r"(a[2]), "r"(a[3]), "r"(b[0]), "r"(b[1]));
}
// Split two fp32 into packed bf16 hi-pair and lo-pair (x in low half).
__device__ __forceinline__ void split2(float x, float y, uint32_t& hi, uint32_t& lo) {
    __nv_bfloat16 xh = __float2bfloat16(x);
    __nv_bfloat16 yh = __float2bfloat16(y);
    __nv_bfloat16 xl = __float2bfloat16(x - __bfloat162float(xh));
    __nv_bfloat16 yl = __float2bfloat16(y - __bfloat162float(yh));
    __nv_bfloat162 h2 = __halves2bfloat162(xh, yh);
    __nv_bfloat162 l2 = __halves2bfloat162(xl, yl);
    hi = *(uint32_t*)&h2;
    lo = *(uint32_t*)&l2;
}
// sigmoid(s/8) = 0.5 * tanh(s/16) + 0.5  (single MUFU.TANH)
__device__ __forceinline__ float sigt(float s) {
    float t;
    asm("tanh.approx.f32 %0, %1;" : "=f"(t) : "f"(s * 0.0625f));
    return fmaf(t, 0.5f, 0.5f);
}

// ---------------------------------------------------------------------------
// One-time fp32 -> bf16 hi/lo split (grid-stride, float4 granularity)
// ---------------------------------------------------------------------------
__global__ void split_kernel(const float* __restrict__ src,
                             __nv_bfloat16* __restrict__ hi,
                             __nv_bfloat16* __restrict__ lo, int n)
{
    for (int i = (blockIdx.x * blockDim.x + threadIdx.x) * 4; i < n;
         i += gridDim.x * blockDim.x * 4) {
        const float4 v = *(const float4*)(src + i);
        uint32_t h0, l0, h1, l1;
        split2(v.x, v.y, h0, l0);
        split2(v.z, v.w, h1, l1);
        *(uint2*)(hi + i) = make_uint2(h0, h1);
        *(uint2*)(lo + i) = make_uint2(l0, l1);
    }
}

// ---------------------------------------------------------------------------
// GEMM core (NT): C[M,N] = A[M,K] * W[N,K]^T + bias[N], bf16x3, pre-split in.
// CTA 128x128, BK=32, 256 threads (8 warps 2x4). cp.async 2-stage pipeline.
// MODE 0: C fp32 row-major. MODE 1: C split bf16 hi/lo, scatter [B,H,S,Dh].
// ---------------------------------------------------------------------------
#define AST 40                      // smem K-stride (32 + 8 pad) bf16
#define GARR (128 * AST)            // elems per array per stage
#define GEMM_SMEM (2 * 4 * GARR * 2)

template <int MODE>
__device__ __forceinline__ void gemm_core(
    const __nv_bfloat16* __restrict__ Ahg, const __nv_bfloat16* __restrict__ Alg,
    const __nv_bfloat16* __restrict__ Whg, const __nv_bfloat16* __restrict__ Wlg,
    const float* __restrict__ bias,
    float* __restrict__ Cf,
    __nv_bfloat16* __restrict__ Ch, __nv_bfloat16* __restrict__ Cl)
{
    extern __shared__ __nv_bfloat16 smg[];
    const int tid  = threadIdx.x;
    const int lane = tid & 31;
    const int wid  = tid >> 5;
    const int wm   = (wid >> 2) * 64;
    const int wn   = (wid & 3) * 32;
    const int bm   = blockIdx.y * 128;
    const int bn   = blockIdx.x * 128;

    int rrow[2], rq[2];
#pragma unroll
    for (int i = 0; i < 2; i++) {
        const int idx = tid + i * 256;
        rrow[i] = idx >> 2;
        rq[i]   = (idx & 3) * 8;
    }

    auto issue = [&](int k0, int s) {
        __nv_bfloat16* sAh = smg + (size_t)s * 4 * GARR;
        __nv_bfloat16* sAl = sAh + GARR;
        __nv_bfloat16* sWh = sAl + GARR;
        __nv_bfloat16* sWl = sWh + GARR;
#pragma unroll
        for (int i = 0; i < 2; i++) {
            const size_t ga = (size_t)(bm + rrow[i]) * D_ + k0 + rq[i];
            const size_t gw = (size_t)(bn + rrow[i]) * D_ + k0 + rq[i];
            const int    so = rrow[i] * AST + rq[i];
            cp16(sAh + so, Ahg + ga);
            cp16(sAl + so, Alg + ga);
            cp16(sWh + so, Whg + gw);
            cp16(sWl + so, Wlg + gw);
        }
    };

    float acc[4][4][4];
#pragma unroll
    for (int mt = 0; mt < 4; mt++)
#pragma unroll
        for (int nt = 0; nt < 4; nt++)
#pragma unroll
            for (int r = 0; r < 4; r++) acc[mt][nt][r] = 0.0f;

    const int a_r = lane & 15;
    const int a_k = (lane >> 4) * 8;
    const int b_r = (lane & 7) + ((lane >> 4) & 1) * 8;
    const int b_k = ((lane >> 3) & 1) * 8;

    issue(0, 0);
    CP_COMMIT();

    const int NCH = D_ / 32;
    for (int kt = 0; kt < NCH; kt++) {
        const int cur = kt & 1;
        if (kt + 1 < NCH) {
            issue((kt + 1) * 32, cur ^ 1);
            CP_COMMIT();
            CP_WAIT(1);
        } else {
            CP_WAIT(0);
        }
        __syncthreads();

        const __nv_bfloat16* sAh = smg + (size_t)cur * 4 * GARR;
        const __nv_bfloat16* sAl = sAh + GARR;
        const __nv_bfloat16* sWh = sAl + GARR;
        const __nv_bfloat16* sWl = sWh + GARR;

#pragma unroll
        for (int ks = 0; ks < 2; ks++) {
            uint32_t Ah[4][4], Al[4][4], Bh[4][2], Bl[4][2];
#pragma unroll
            for (int mt = 0; mt < 4; mt++) {
                const int eo = (wm + mt * 16 + a_r) * AST + ks * 16 + a_k;
                ldsm_x4(Ah[mt][0], Ah[mt][1], Ah[mt][2], Ah[mt][3], smem_u32(&sAh[eo]));
                ldsm_x4(Al[mt][0], Al[mt][1], Al[mt][2], Al[mt][3], smem_u32(&sAl[eo]));
            }
#pragma unroll
            for (int p = 0; p < 2; p++) {
                const int eo = (wn + p * 16 + b_r) * AST + ks * 16 + b_k;
                ldsm_x4(Bh[2 * p][0], Bh[2 * p][1], Bh[2 * p + 1][0], Bh[2 * p + 1][1],
                        smem_u32(&sWh[eo]));
                ldsm_x4(Bl[2 * p][0], Bl[2 * p][1], Bl[2 * p + 1][0], Bl[2 * p + 1][1],
                        smem_u32(&sWl[eo]));
            }
#pragma unroll
            for (int mt = 0; mt < 4; mt++)
#pragma unroll
                for (int nt = 0; nt < 4; nt++) {
                    mma_bf16(acc[mt][nt], Ah[mt], Bh[nt]);
                    mma_bf16(acc[mt][nt], Ah[mt], Bl[nt]);
                    mma_bf16(acc[mt][nt], Al[mt], Bh[nt]);
                }
        }
        __syncthreads();
    }

#pragma unroll
    for (int mt = 0; mt < 4; mt++) {
        const int r0 = bm + wm + mt * 16 + (lane >> 2);
#pragma unroll
        for (int nt = 0; nt < 4; nt++) {
            const int c0 = bn + wn + nt * 8 + (lane & 3) * 2;
            const float bz0 = bias[c0], bz1 = bias[c0 + 1];
#pragma unroll
            for (int half = 0; half < 2; half++) {
                const int row = r0 + half * 8;
                const float v0 = acc[mt][nt][2 * half]     + bz0;
                const float v1 = acc[mt][nt][2 * half + 1] + bz1;
                if (MODE == 0) {
                    *(float2*)&Cf[(size_t)row * D_ + c0] = make_float2(v0, v1);
                } else {
                    const int bb = row >> 11;
                    const int ss = row & (S_ - 1);
                    const int h  = c0 >> 6;
                    const int dh = c0 & (DH_ - 1);
                    const size_t o = (((size_t)(bb * H_ + h)) * S_ + ss) * DH_ + dh;
                    uint32_t hi, lo;
                    split2(v0, v1, hi, lo);
                    *(uint32_t*)&Ch[o] = hi;
                    *(uint32_t*)&Cl[o] = lo;
                }
            }
        }
    }
}

struct ProjArgs {
    const __nv_bfloat16 *Ah[3], *Al[3], *Wh[3], *Wl[3];
    const float* bias[3];
    __nv_bfloat16 *Ch[3], *Cl[3];
};

__global__ __launch_bounds__(256) void gemm_proj(ProjArgs pa)
{
    const int z = blockIdx.z;
    gemm_core<1>(pa.Ah[z], pa.Al[z], pa.Wh[z], pa.Wl[z], pa.bias[z],
                 nullptr, pa.Ch[z], pa.Cl[z]);
}

__global__ __launch_bounds__(256) void gemm_out(
    const __nv_bfloat16* __restrict__ Ah, const __nv_bfloat16* __restrict__ Al,
    const __nv_bfloat16* __restrict__ Wh, const __nv_bfloat16* __restrict__ Wl,
    const float* __restrict__ bias, float* __restrict__ C)
{
    gemm_core<0>(Ah, Al, Wh, Wl, bias, C, nullptr, nullptr);
}

// ---------------------------------------------------------------------------
// Sigmoid attention, FA2-style, FUSED mainloop.
// Per (b,h): O = sigmoid(QK^T/8) V. Warp = 16 q-rows x 128 kv.
// Per 16-kv block: 24 MMAs (QK^T) -> 8 tanh-sigmoids -> 24 MMAs (PV), so
// MUFU/cvt work interleaves with MMAs instead of forming a chip-wide bubble.
// Single-buffered K/V (cp.async), 2 CTAs/SM (smem 110.6 KB, regs <= 128).
// ---------------------------------------------------------------------------
#define QST 72
#define SARR (128 * QST)
#define ATT_SMEM (6 * SARR * 2)   // 110,592 B

__global__ __launch_bounds__(256, 2) void attn_fa(
    const __nv_bfloat16* __restrict__ Qh_g, const __nv_bfloat16* __restrict__ Ql_g,
    const __nv_bfloat16* __restrict__ Kh_g, const __nv_bfloat16* __restrict__ Kl_g,
    const __nv_bfloat16* __restrict__ Vh_g, const __nv_bfloat16* __restrict__ Vl_g,
    __nv_bfloat16* __restrict__ Oh_g, __nv_bfloat16* __restrict__ Ol_g)
{
    extern __shared__ __nv_bfloat16 sm[];
    __nv_bfloat16* Qh = sm;
    __nv_bfloat16* Ql = Qh + SARR;
    __nv_bfloat16* Kh = Ql + SARR;
    __nv_bfloat16* Kl = Kh + SARR;
    __nv_bfloat16* Vh = Kl + SARR;
    __nv_bfloat16* Vl = Vh + SARR;

    const int tid  = threadIdx.x;
    const int lane = tid & 31;
    const int wid  = tid >> 5;
    const int r0   = wid * 16;
    const int bh   = blockIdx.y;
    const int q0   = blockIdx.x * 128;

    const size_t base = (size_t)bh * S_ * DH_;
    const __nv_bfloat16* Qph = Qh_g + base;
    const __nv_bfloat16* Qpl = Ql_g + base;
    const __nv_bfloat16* Kph = Kh_g + base;
    const __nv_bfloat16* Kpl = Kl_g + base;
    const __nv_bfloat16* Vph = Vh_g + base;
    const __nv_bfloat16* Vpl = Vl_g + base;

    int srow[4], sq[4];
#pragma unroll
    for (int i = 0; i < 4; i++) {
        const int idx = tid + i * 256;
        srow[i] = idx >> 3;
        sq[i]   = (idx & 7) * 8;
    }

    auto issue_kv = [&](int j0) {
#pragma unroll
        for (int i = 0; i < 4; i++) {
            const size_t go = (size_t)(j0 + srow[i]) * DH_ + sq[i];
            const int    so = srow[i] * QST + sq[i];
            cp16(Kh + so, Kph + go);
            cp16(Kl + so, Kpl + go);
            cp16(Vh + so, Vph + go);
            cp16(Vl + so, Vpl + go);
        }
    };

    // prologue: async Q + tile 0
#pragma unroll
    for (int i = 0; i < 4; i++) {
        const size_t go = (size_t)(q0 + srow[i]) * DH_ + sq[i];
        const int    so = srow[i] * QST + sq[i];
        cp16(Qh + so, Qph + go);
        cp16(Ql + so, Qpl + go);
    }
    issue_kv(0);
    CP_COMMIT();

    const int a_r = lane & 15;
    const int a_k = (lane >> 4) * 8;
    const int b_r = (lane & 7) + ((lane >> 4) & 1) * 8;
    const int b_k = ((lane >> 3) & 1) * 8;
    const int v_kv = lane & 15;
    const int v_dh = ((lane >> 4) & 1) * 8;

    uint32_t Qfh[4][4], Qfl[4][4];   // Q fragments, loaded once (tile-invariant)
    float oacc[8][4];
#pragma unroll
    for (int t = 0; t < 8; t++)
#pragma unroll
        for (int r = 0; r < 4; r++) oacc[t][r] = 0.0f;

    const int NT = S_ / 128;
    for (int jt = 0; jt < NT; jt++) {
        CP_WAIT(0);
        __syncthreads();

        if (jt == 0) {
#pragma unroll
            for (int ks = 0; ks < 4; ks++) {
                const int eo = (r0 + a_r) * QST + ks * 16 + a_k;
                ldsm_x4(Qfh[ks][0], Qfh[ks][1], Qfh[ks][2], Qfh[ks][3], smem_u32(&Qh[eo]));
                ldsm_x4(Qfl[ks][0], Qfl[ks][1], Qfl[ks][2], Qfl[ks][3], smem_u32(&Ql[eo]));
            }
        }

        // fused per-16-kv-block loop
#pragma unroll 2
        for (int kt = 0; kt < 8; kt++) {
            float sacc[2][4];
#pragma unroll
            for (int t = 0; t < 2; t++)
#pragma unroll
                for (int r = 0; r < 4; r++) sacc[t][r] = 0.0f;

#pragma unroll
            for (int ks = 0; ks < 4; ks++) {
                uint32_t Bh0[2], Bh1[2], Bl0[2], Bl1[2];
                const int eo = (kt * 16 + b_r) * QST + ks * 16 + b_k;
                ldsm_x4(Bh0[0], Bh0[1], Bh1[0], Bh1[1], smem_u32(&Kh[eo]));
                ldsm_x4(Bl0[0], Bl0[1], Bl1[0], Bl1[1], smem_u32(&Kl[eo]));
                mma_bf16(sacc[0], Qfh[ks], Bh0);
                mma_bf16(sacc[0], Qfh[ks], Bl0);
                mma_bf16(sacc[0], Qfl[ks], Bh0);
                mma_bf16(sacc[1], Qfh[ks], Bh1);
                mma_bf16(sacc[1], Qfh[ks], Bl1);
                mma_bf16(sacc[1], Qfl[ks], Bh1);
            }

            // sigmoid + repack accumulator fragment -> A-operand fragment
            uint32_t Pfh[4], Pfl[4];
            {
                const float p00 = sigt(sacc[0][0]), p01 = sigt(sacc[0][1]);
                const float p02 = sigt(sacc[0][2]), p03 = sigt(sacc[0][3]);
                const float p10 = sigt(sacc[1][0]), p11 = sigt(sacc[1][1]);
                const float p12 = sigt(sacc[1][2]), p13 = sigt(sacc[1][3]);
                split2(p00, p01, Pfh[0], Pfl[0]);
                split2(p02, p03, Pfh[1], Pfl[1]);
                split2(p10, p11, Pfh[2], Pfl[2]);
                split2(p12, p13, Pfh[3], Pfl[3]);
            }

#pragma unroll
            for (int nn = 0; nn < 4; nn++) {
                uint32_t Bh0[2], Bh1[2], Bl0[2], Bl1[2];
                const int eo = (kt * 16 + v_kv) * QST + nn * 16 + v_dh;
                ldsm_x4t(Bh0[0], Bh0[1], Bh1[0], Bh1[1], smem_u32(&Vh[eo]));
                ldsm_x4t(Bl0[0], Bl0[1], Bl1[0], Bl1[1], smem_u32(&Vl[eo]));
                mma_bf16(oacc[2 * nn],     Pfh, Bh0);
                mma_bf16(oacc[2 * nn],     Pfh, Bl0);
                mma_bf16(oacc[2 * nn],     Pfl, Bh0);
                mma_bf16(oacc[2 * nn + 1], Pfh, Bh1);
                mma_bf16(oacc[2 * nn + 1], Pfh, Bl1);
                mma_bf16(oacc[2 * nn + 1], Pfl, Bh1);
            }
        }

        __syncthreads();
        if (jt + 1 < NT) {
            issue_kv((jt + 1) * 128);
            CP_COMMIT();
        }
    }

    // epilogue: split O -> hi/lo bf16, concat layout [B,S,D]
    const int bb = bh >> 4;
    const int h  = bh & (H_ - 1);
    const int g  = lane >> 2;
    const int c2 = (lane & 3) * 2;
#pragma unroll
    for (int t = 0; t < 8; t++) {
        const int dh = 8 * t + c2;
#pragma unroll
        for (int half = 0; half < 2; half++) {
            const int srw = q0 + r0 + g + half * 8;
            const size_t o = ((size_t)bb * S_ + srw) * D_ + h * DH_ + dh;
            uint32_t hi, lo;
            split2(oacc[t][2 * half], oacc[t][2 * half + 1], hi, lo);
            *(uint32_t*)&Oh_g[o] = hi;
            *(uint32_t*)&Ol_g[o] = lo;
        }
    }
}

// ---------------------------------------------------------------------------
// Launcher
// ---------------------------------------------------------------------------
extern "C" void kernel_launch(void* const* d_in, const int* in_sizes, int n_in,
                              void* d_out, int out_size)
{
    const float* q  = (const float*)d_in[0];
    const float* k  = (const float*)d_in[1];
    const float* v  = (const float*)d_in[2];
    const float* Wq = (const float*)d_in[3];
    const float* bq = (const float*)d_in[4];
    const float* Wk = (const float*)d_in[5];
    const float* bk = (const float*)d_in[6];
    const float* Wv = (const float*)d_in[7];
    const float* bv = (const float*)d_in[8];
    const float* Wo = (const float*)d_in[9];
    const float* bo = (const float*)d_in[10];
    float* out = (float*)d_out;

    __nv_bfloat16 *inh, *inl, *wh, *wl, *ph, *pl, *oh, *ol;
    cudaGetSymbolAddress((void**)&inh, g_inh);
    cudaGetSymbolAddress((void**)&inl, g_inl);
    cudaGetSymbolAddress((void**)&wh,  g_wh);
    cudaGetSymbolAddress((void**)&wl,  g_wl);
    cudaGetSymbolAddress((void**)&ph,  g_ph);
    cudaGetSymbolAddress((void**)&pl,  g_pl);
    cudaGetSymbolAddress((void**)&oh,  g_oh);
    cudaGetSymbolAddress((void**)&ol,  g_ol);

    // one-time splits
    split_kernel<<<2048, 256>>>(q,  inh + 0 * MD_, inl + 0 * MD_, MD_);
    split_kernel<<<2048, 256>>>(k,  inh + 1 * MD_, inl + 1 * MD_, MD_);
    split_kernel<<<2048, 256>>>(v,  inh + 2 * MD_, inl + 2 * MD_, MD_);
    split_kernel<<<512, 256>>>(Wq, wh + 0 * DD_, wl + 0 * DD_, DD_);
    split_kernel<<<512, 256>>>(Wk, wh + 1 * DD_, wl + 1 * DD_, DD_);
    split_kernel<<<512, 256>>>(Wv, wh + 2 * DD_, wl + 2 * DD_, DD_);
    split_kernel<<<512, 256>>>(Wo, wh + 3 * DD_, wl + 3 * DD_, DD_);

    // fused Q/K/V projections (grid.z = 3)
    ProjArgs pa;
    const float* biases[3] = {bq, bk, bv};
    for (int z = 0; z < 3; z++) {
        pa.Ah[z] = inh + (size_t)z * MD_;
        pa.Al[z] = inl + (size_t)z * MD_;
        pa.Wh[z] = wh + (size_t)z * DD_;
        pa.Wl[z] = wl + (size_t)z * DD_;
        pa.bias[z] = biases[z];
        pa.Ch[z] = ph + (size_t)z * MD_;
        pa.Cl[z] = pl + (size_t)z * MD_;
    }
    cudaFuncSetAttribute(gemm_proj, cudaFuncAttributeMaxDynamicSharedMemorySize, GEMM_SMEM);
    gemm_proj<<<dim3(D_ / 128, M_ / 128, 3), 256, GEMM_SMEM>>>(pa);

    // attention
    cudaFuncSetAttribute(attn_fa, cudaFuncAttributeMaxDynamicSharedMemorySize, ATT_SMEM);
    attn_fa<<<dim3(S_ / 128, B_ * H_), 256, ATT_SMEM>>>(
        ph + 0 * MD_, pl + 0 * MD_,
        ph + 1 * MD_, pl + 1 * MD_,
        ph + 2 * MD_, pl + 2 * MD_,
        oh, ol);

    // output projection
    cudaFuncSetAttribute(gemm_out, cudaFuncAttributeMaxDynamicSharedMemorySize, GEMM_SMEM);
    gemm_out<<<dim3(D_ / 128, M_ / 128), 256, GEMM_SMEM>>>(
        oh, ol, wh + 3 * DD_, wl + 3 * DD_, bo, out);
}